// round 1
// baseline (speedup 1.0000x reference)
#include <cuda_runtime.h>
#include <cuda_bf16.h>
#include <math.h>

// SingleValueAgent: v_t = v_{t-1} + alpha*(x_t - v_{t-1}), x_t = c_t*o_t, v_0 = 0
// Outputs: out=v_t, diff=x_t - v_{t-1}, delta=alpha*diff, concatenated [out|diff|delta].
//
// Parallel scan over the constant-decay linear recurrence:
//   block = 1 session (2048 trials), 256 threads x 8 trials/thread.
//   thread-local partial (v_in=0) -> weighted Hillis-Steele scan -> replay.

#define TRIALS   2048
#define THREADS  256
#define PER      (TRIALS / THREADS)   // 8

__global__ __launch_bounds__(THREADS)
void sva_kernel(const float* __restrict__ inp,     // (n_sess, TRIALS, 2)
                const float* __restrict__ a_raw,   // (1,)
                float* __restrict__ out,           // 3 * n_sess * TRIALS
                long long n_elems)                 // n_sess * TRIALS
{
    const int sess = blockIdx.x;
    const int t    = threadIdx.x;

    // alpha = sigmoid(a_raw)
    const float alpha = 1.0f / (1.0f + __expf(-a_raw[0]));
    const float am    = 1.0f - alpha;

    // Load this thread's 8 trials (64B contiguous per thread; full sectors).
    const float2* __restrict__ xin =
        reinterpret_cast<const float2*>(inp) + (long long)sess * TRIALS + t * PER;

    float x[PER];
#pragma unroll
    for (int i = 0; i < PER; i++) {
        float2 c = xin[i];
        x[i] = c.x * c.y;
    }

    // Local partial with v_in = 0: p <- p + alpha*(x - p)  (== am*p + alpha*x)
    float p = 0.0f;
#pragma unroll
    for (int i = 0; i < PER; i++) {
        p = p + alpha * (x[i] - p);
    }

    // am^PER (PER == 8)
    float a2 = am * am;
    float a4 = a2 * a2;
    float a8 = a4 * a4;

    // Weighted inclusive Hillis-Steele scan across the 256 threads:
    // invariant after offset o: s[t] = sum_{j in window} a8^(t-j) * p_j
    __shared__ float s[THREADS];
    float acc = p;
    s[t] = acc;
    __syncthreads();

    float w = a8; // a8^o for current offset o
#pragma unroll
    for (int o = 1; o < THREADS; o <<= 1) {
        float prev = (t >= o) ? s[t - o] : 0.0f;
        __syncthreads();
        acc += w * prev;
        s[t] = acc;
        w *= w;
        __syncthreads();
    }

    // v entering this thread's chunk = inclusive scan of chunks [0, t-1]
    float v = (t > 0) ? s[t - 1] : 0.0f;

    // Replay and write all three outputs (each thread writes one 32B sector/array).
    const long long base = (long long)sess * TRIALS + t * PER;
    float* __restrict__ o_v = out + base;
    float* __restrict__ o_d = out + n_elems + base;
    float* __restrict__ o_e = out + 2 * n_elems + base;

    float vv[PER], dd[PER], ee[PER];
#pragma unroll
    for (int i = 0; i < PER; i++) {
        float diff  = x[i] - v;
        float delta = alpha * diff;
        v = v + delta;
        vv[i] = v; dd[i] = diff; ee[i] = delta;
    }

    // 32B vectorized stores (float4 pairs)
#pragma unroll
    for (int i = 0; i < PER; i += 4) {
        *reinterpret_cast<float4*>(o_v + i) = make_float4(vv[i], vv[i+1], vv[i+2], vv[i+3]);
        *reinterpret_cast<float4*>(o_d + i) = make_float4(dd[i], dd[i+1], dd[i+2], dd[i+3]);
        *reinterpret_cast<float4*>(o_e + i) = make_float4(ee[i], ee[i+1], ee[i+2], ee[i+3]);
    }
}

extern "C" void kernel_launch(void* const* d_in, const int* in_sizes, int n_in,
                              void* d_out, int out_size)
{
    const float* inp   = (const float*)d_in[0];   // (n_sess, 2048, 2) float32
    const float* a_raw = (const float*)d_in[1];   // (1,) float32
    float* out = (float*)d_out;

    const long long n_elems = (long long)in_sizes[0] / 2;       // n_sess * TRIALS
    const int n_sess = (int)(n_elems / TRIALS);

    sva_kernel<<<n_sess, THREADS>>>(inp, a_raw, out, n_elems);
}

// round 2
// speedup vs baseline: 1.0599x; 1.0599x over previous
#include <cuda_runtime.h>
#include <cuda_bf16.h>
#include <math.h>

// SingleValueAgent: v_t = v_{t-1} + alpha*(x_t - v_{t-1}), x_t = c_t*o_t, v_0 = 0
// Outputs concatenated [v | diff | delta], each (n_sess, 2048, 1) fp32.
//
// Per-session parallel scan of the constant-decay linear recurrence.
// Block = 1 session; 256 threads x 8 trials. Warp-shuffle weighted scan
// (no smem rounds, 1 barrier) + streaming cache hints.

#define TRIALS   2048
#define THREADS  256
#define PER      8
#define NWARP    (THREADS / 32)

__global__ __launch_bounds__(THREADS)
void sva_kernel(const float* __restrict__ inp,     // (n_sess, TRIALS, 2)
                const float* __restrict__ a_raw,   // (1,)
                float* __restrict__ out,           // 3 * n_sess * TRIALS
                long long n_elems)                 // n_sess * TRIALS
{
    const int sess = blockIdx.x;
    const int t    = threadIdx.x;
    const int lane = t & 31;
    const int wid  = t >> 5;

    const float alpha = 1.0f / (1.0f + __expf(-a_raw[0]));
    const float am    = 1.0f - alpha;

    // ---- Load 8 trials = 64B contiguous, as 4 x float4 (streaming) ----
    const float4* __restrict__ xin = reinterpret_cast<const float4*>(
        inp + ((long long)sess * TRIALS + (long long)t * PER) * 2);

    float x[PER];
#pragma unroll
    for (int i = 0; i < 4; i++) {
        float4 c = __ldcs(&xin[i]);     // {c0,o0,c1,o1}
        x[2*i]   = c.x * c.y;
        x[2*i+1] = c.z * c.w;
    }

    // ---- Thread-local partial with v_in = 0 ----
    float p = 0.0f;
#pragma unroll
    for (int i = 0; i < PER; i++) {
        p = fmaf(alpha, x[i] - p, p);
    }

    const float a2 = am * am;
    const float a4 = a2 * a2;
    const float a8 = a4 * a4;           // decay of one 8-trial chunk

    // ---- Warp weighted inclusive scan (Hillis-Steele via shfl) ----
    // invariant after offset o: acc[l] = sum_{j in window} a8^(l-j) p_j
    float acc = p;
    float wgt = a8;                     // a8^o for current offset
#pragma unroll
    for (int o = 1; o < 32; o <<= 1) {
        float prev = __shfl_up_sync(0xffffffffu, acc, o);
        if (lane >= o) acc = fmaf(wgt, prev, acc);
        wgt *= wgt;
    }
    const float a256 = wgt;             // a8^32: decay of one warp (256 trials)

    // ---- Cross-warp combine: one smem word per warp, one barrier ----
    __shared__ float warpT[NWARP];
    if (lane == 31) warpT[wid] = acc;
    __syncthreads();

    // E[w] = sum_{u<w} a256^(w-1-u) * T_u   (exclusive weighted prefix)
    float E = 0.0f;
#pragma unroll
    for (int u = 0; u < NWARP - 1; u++) {
        if (u < wid) E = fmaf(E, a256, warpT[u]);
    }

    // s_local[lane-1] (exclusive within warp)
    float excl = __shfl_up_sync(0xffffffffu, acc, 1);
    if (lane == 0) excl = 0.0f;

    // a8^lane via binary exponentiation (5 steps)
    float apow = 1.0f, b = a8;
#pragma unroll
    for (int k = 0; k < 5; k++) {
        if (lane & (1 << k)) apow *= b;
        b *= b;
    }

    // v entering this thread's 8-trial chunk
    float v = fmaf(apow, E, excl);

    // ---- Replay & write all three outputs ----
    const long long base = (long long)sess * TRIALS + (long long)t * PER;
    float* __restrict__ o_v = out + base;
    float* __restrict__ o_d = out + n_elems + base;
    float* __restrict__ o_e = out + 2 * n_elems + base;

    float vv[PER], dd[PER], ee[PER];
#pragma unroll
    for (int i = 0; i < PER; i++) {
        float diff  = x[i] - v;
        float delta = alpha * diff;
        v = v + delta;
        vv[i] = v; dd[i] = diff; ee[i] = delta;
    }

#pragma unroll
    for (int i = 0; i < PER; i += 4) {
        __stcs(reinterpret_cast<float4*>(o_v + i),
               make_float4(vv[i], vv[i+1], vv[i+2], vv[i+3]));
        __stcs(reinterpret_cast<float4*>(o_d + i),
               make_float4(dd[i], dd[i+1], dd[i+2], dd[i+3]));
        __stcs(reinterpret_cast<float4*>(o_e + i),
               make_float4(ee[i], ee[i+1], ee[i+2], ee[i+3]));
    }
}

extern "C" void kernel_launch(void* const* d_in, const int* in_sizes, int n_in,
                              void* d_out, int out_size)
{
    const float* inp   = (const float*)d_in[0];   // (n_sess, 2048, 2) float32
    const float* a_raw = (const float*)d_in[1];   // (1,) float32
    float* out = (float*)d_out;

    const long long n_elems = (long long)in_sizes[0] / 2;   // n_sess * TRIALS
    const int n_sess = (int)(n_elems / TRIALS);

    sva_kernel<<<n_sess, THREADS>>>(inp, a_raw, out, n_elems);
}

// round 3
// speedup vs baseline: 1.2244x; 1.1552x over previous
#include <cuda_runtime.h>
#include <cuda_bf16.h>
#include <math.h>

// SingleValueAgent: v_t = v_{t-1} + alpha*(x_t - v_{t-1}), x_t = c_t*o_t, v_0 = 0
// Outputs concatenated [v | diff | delta], each (n_sess, 2048, 1) fp32.
//
// Block = 1 session; 512 threads x 4 trials. PER=4 makes every output store
// exactly one STG.128 at 16B lane stride -> 1 L1 sector-access per sector
// (PER=8 caused 2x sector-access on all streams; L1tex was the binding pipe).

#define TRIALS   2048
#define THREADS  512
#define PER      4
#define NWARP    (THREADS / 32)   // 16

__global__ __launch_bounds__(THREADS)
void sva_kernel(const float* __restrict__ inp,     // (n_sess, TRIALS, 2)
                const float* __restrict__ a_raw,   // (1,)
                float* __restrict__ out,           // 3 * n_sess * TRIALS
                long long n_elems)                 // n_sess * TRIALS
{
    const int sess = blockIdx.x;
    const int t    = threadIdx.x;
    const int lane = t & 31;
    const int wid  = t >> 5;

    const float alpha = 1.0f / (1.0f + __expf(-a_raw[0]));
    const float am    = 1.0f - alpha;

    // ---- Load 4 trials = 32B contiguous, as 2 x float4 (streaming) ----
    const float4* __restrict__ xin = reinterpret_cast<const float4*>(
        inp + ((long long)sess * TRIALS + (long long)t * PER) * 2);

    float4 c0 = __ldcs(&xin[0]);        // {c0,o0,c1,o1}
    float4 c1 = __ldcs(&xin[1]);        // {c2,o2,c3,o3}

    float x[PER];
    x[0] = c0.x * c0.y;
    x[1] = c0.z * c0.w;
    x[2] = c1.x * c1.y;
    x[3] = c1.z * c1.w;

    // ---- Thread-local partial with v_in = 0 ----
    float p = 0.0f;
#pragma unroll
    for (int i = 0; i < PER; i++) {
        p = fmaf(alpha, x[i] - p, p);
    }

    const float a2 = am * am;
    const float a4 = a2 * a2;           // decay of one 4-trial chunk

    // ---- Warp weighted inclusive scan (Hillis-Steele via shfl) ----
    float acc = p;
    float wgt = a4;
#pragma unroll
    for (int o = 1; o < 32; o <<= 1) {
        float prev = __shfl_up_sync(0xffffffffu, acc, o);
        if (lane >= o) acc = fmaf(wgt, prev, acc);
        wgt *= wgt;
    }
    const float awarp = wgt;            // a4^32 = am^128: decay of one warp

    // ---- Cross-warp combine: one smem word per warp, one barrier ----
    __shared__ float warpT[NWARP];
    if (lane == 31) warpT[wid] = acc;
    __syncthreads();

    // E[w] = sum_{u<w} awarp^(w-1-u) * T_u   (exclusive weighted prefix)
    float E = 0.0f;
#pragma unroll
    for (int u = 0; u < NWARP - 1; u++) {
        if (u < wid) E = fmaf(E, awarp, warpT[u]);
    }

    // exclusive within-warp prefix
    float excl = __shfl_up_sync(0xffffffffu, acc, 1);
    if (lane == 0) excl = 0.0f;

    // a4^lane via binary exponentiation (5 steps)
    float apow = 1.0f, b = a4;
#pragma unroll
    for (int k = 0; k < 5; k++) {
        if (lane & (1 << k)) apow *= b;
        b *= b;
    }

    // v entering this thread's 4-trial chunk
    float v = fmaf(apow, E, excl);

    // ---- Replay & write: exactly one STG.128 per output array ----
    const long long base = (long long)sess * TRIALS + (long long)t * PER;

    float vv[PER], dd[PER], ee[PER];
#pragma unroll
    for (int i = 0; i < PER; i++) {
        float diff  = x[i] - v;
        float delta = alpha * diff;
        v = v + delta;
        vv[i] = v; dd[i] = diff; ee[i] = delta;
    }

    __stcs(reinterpret_cast<float4*>(out + base),
           make_float4(vv[0], vv[1], vv[2], vv[3]));
    __stcs(reinterpret_cast<float4*>(out + n_elems + base),
           make_float4(dd[0], dd[1], dd[2], dd[3]));
    __stcs(reinterpret_cast<float4*>(out + 2 * n_elems + base),
           make_float4(ee[0], ee[1], ee[2], ee[3]));
}

extern "C" void kernel_launch(void* const* d_in, const int* in_sizes, int n_in,
                              void* d_out, int out_size)
{
    const float* inp   = (const float*)d_in[0];   // (n_sess, 2048, 2) float32
    const float* a_raw = (const float*)d_in[1];   // (1,) float32
    float* out = (float*)d_out;

    const long long n_elems = (long long)in_sizes[0] / 2;   // n_sess * TRIALS
    const int n_sess = (int)(n_elems / TRIALS);

    sva_kernel<<<n_sess, THREADS>>>(inp, a_raw, out, n_elems);
}

// round 4
// speedup vs baseline: 1.2562x; 1.0260x over previous
#include <cuda_runtime.h>
#include <cuda_bf16.h>
#include <math.h>

// SingleValueAgent: v_t = v_{t-1} + alpha*(x_t - v_{t-1}), x_t = c_t*o_t, v_0 = 0
// Outputs concatenated [v | diff | delta], each (n_sess, 2048, 1) fp32.
//
// Block = 1 session; 512 threads x 4 trials.
//  - Outputs: one STG.128 per array at 16B lane stride (1 L1 access/sector).
//  - Inputs: coalesced LDG.128 at 16B lane stride + 8-shuffle warp transpose
//    so each thread owns 4 consecutive trials (R3 pattern paid 2 accesses/sector).
//  - Weighted warp-shuffle scan + 16-warp smem combine, one barrier.

#define TRIALS   2048
#define THREADS  512
#define PER      4
#define NWARP    (THREADS / 32)   // 16

__global__ __launch_bounds__(THREADS)
void sva_kernel(const float* __restrict__ inp,     // (n_sess, TRIALS, 2)
                const float* __restrict__ a_raw,   // (1,)
                float* __restrict__ out,           // 3 * n_sess * TRIALS
                long long n_elems)                 // n_sess * TRIALS
{
    const int sess = blockIdx.x;
    const int t    = threadIdx.x;
    const int lane = t & 31;
    const int wid  = t >> 5;

    const float alpha = 1.0f / (1.0f + __expf(-a_raw[0]));
    const float am    = 1.0f - alpha;

    // ---- Coalesced input load: warp covers 128 trials = 64 float4s ----
    // float4 #k = trials {2k, 2k+1}. Batch A = first 32 float4s, batch B = last 32.
    const float4* __restrict__ xin = reinterpret_cast<const float4*>(inp);
    const long long warpF = (long long)sess * (TRIALS / 2) + (long long)wid * 64;

    float4 cA = __ldcs(&xin[warpF + lane]);        // trials {2l, 2l+1}   (warp-local)
    float4 cB = __ldcs(&xin[warpF + 32 + lane]);   // trials {64+2l, 65+2l}

    float a0 = cA.x * cA.y, a1 = cA.z * cA.w;
    float b0 = cB.x * cB.y, b1 = cB.z * cB.w;

    // ---- Warp transpose: thread l wants warp-local trials 4l..4l+3 ----
    // sources: lanes s0=(2l)&31, s1=s0+1; batch A if l<16 else batch B.
    const int s0 = (2 * lane) & 31;
    const int s1 = s0 + 1;
    const unsigned FULL = 0xffffffffu;

    float A00 = __shfl_sync(FULL, a0, s0);
    float A01 = __shfl_sync(FULL, a1, s0);
    float A10 = __shfl_sync(FULL, a0, s1);
    float A11 = __shfl_sync(FULL, a1, s1);
    float B00 = __shfl_sync(FULL, b0, s0);
    float B01 = __shfl_sync(FULL, b1, s0);
    float B10 = __shfl_sync(FULL, b0, s1);
    float B11 = __shfl_sync(FULL, b1, s1);

    const bool lo = (lane < 16);
    float x[PER];
    x[0] = lo ? A00 : B00;
    x[1] = lo ? A01 : B01;
    x[2] = lo ? A10 : B10;
    x[3] = lo ? A11 : B11;

    // ---- Thread-local partial with v_in = 0 ----
    float p = 0.0f;
#pragma unroll
    for (int i = 0; i < PER; i++) {
        p = fmaf(alpha, x[i] - p, p);
    }

    const float a2 = am * am;
    const float a4 = a2 * a2;           // decay of one 4-trial chunk

    // ---- Warp weighted inclusive scan (Hillis-Steele via shfl) ----
    float acc = p;
    float wgt = a4;
#pragma unroll
    for (int o = 1; o < 32; o <<= 1) {
        float prev = __shfl_up_sync(FULL, acc, o);
        if (lane >= o) acc = fmaf(wgt, prev, acc);
        wgt *= wgt;
    }
    const float awarp = wgt;            // am^128: decay of one warp

    // ---- Cross-warp combine: one smem word per warp, one barrier ----
    __shared__ float warpT[NWARP];
    if (lane == 31) warpT[wid] = acc;
    __syncthreads();

    // E[w] = sum_{u<w} awarp^(w-1-u) * T_u   (exclusive weighted prefix)
    float E = 0.0f;
#pragma unroll
    for (int u = 0; u < NWARP - 1; u++) {
        if (u < wid) E = fmaf(E, awarp, warpT[u]);
    }

    // exclusive within-warp prefix
    float excl = __shfl_up_sync(FULL, acc, 1);
    if (lane == 0) excl = 0.0f;

    // a4^lane via binary exponentiation (5 steps)
    float apow = 1.0f, b = a4;
#pragma unroll
    for (int k = 0; k < 5; k++) {
        if (lane & (1 << k)) apow *= b;
        b *= b;
    }

    // v entering this thread's 4-trial chunk
    float v = fmaf(apow, E, excl);

    // ---- Replay & write: one STG.128 per output array ----
    const long long base = (long long)sess * TRIALS + (long long)t * PER;

    float vv[PER], dd[PER], ee[PER];
#pragma unroll
    for (int i = 0; i < PER; i++) {
        float diff  = x[i] - v;
        float delta = alpha * diff;
        v = v + delta;
        vv[i] = v; dd[i] = diff; ee[i] = delta;
    }

    __stcs(reinterpret_cast<float4*>(out + base),
           make_float4(vv[0], vv[1], vv[2], vv[3]));
    __stcs(reinterpret_cast<float4*>(out + n_elems + base),
           make_float4(dd[0], dd[1], dd[2], dd[3]));
    __stcs(reinterpret_cast<float4*>(out + 2 * n_elems + base),
           make_float4(ee[0], ee[1], ee[2], ee[3]));
}

extern "C" void kernel_launch(void* const* d_in, const int* in_sizes, int n_in,
                              void* d_out, int out_size)
{
    const float* inp   = (const float*)d_in[0];   // (n_sess, 2048, 2) float32
    const float* a_raw = (const float*)d_in[1];   // (1,) float32
    float* out = (float*)d_out;

    const long long n_elems = (long long)in_sizes[0] / 2;   // n_sess * TRIALS
    const int n_sess = (int)(n_elems / TRIALS);

    sva_kernel<<<n_sess, THREADS>>>(inp, a_raw, out, n_elems);
}